// round 17
// baseline (speedup 1.0000x reference)
#include <cuda_runtime.h>
#include <cuda_fp16.h>
#include <math.h>
#include <stdint.h>

// ---------------- problem constants ----------------
#define BATCH   2
#define SEQ     2048
#define BT      (BATCH*SEQ)      // 4096 rows
#define DMODEL  768
#define DINNER  1536
#define NHEADS  24
#define DHEAD   64
#define DSTATE  8
#define DCONV   4
#define DPROJ   3120             // 2*DINNER + NHEADS*2
#define DGV     3072             // gate+vraw fp16 region width
#define NPAR    48               // params columns (f32 side buffer)
#define DFF     3072

// transposed weight scratch offsets (halves); layout [N][K]
#define W_IN_OFF  0
#define W_BC_OFF  2396160                       // 768*3120
#define W_OUT_OFF 2985984                       // + 1536*384
#define FF1_OFF   4165632                       // + 1536*768
#define FF2_OFF   6524928                       // + 768*3072
#define W_TOTAL   8884224                       // + 3072*768

// merged-transpose tile ranges (32x32 tiles, Nt = tiles along N)
#define T1_END 2352      // w_in : 98*24
#define T2_END 2928      // w_bc : 12*48
#define T3_END 4080      // w_out: 24*48
#define T4_END 6384      // ff1  : 96*24
#define T5_END 8688      // ff2  : 24*96
#define TR_BLOCKS (T5_END + BT)   // + rmsnorm1 blocks (fused)

// ---------------- scratch (static device globals; no allocation) ----------------
__device__ float  g_bc  [BT*2*NHEADS*DSTATE];
__device__ float  g_Bn  [BT*NHEADS*DSTATE];
__device__ float  g_Cn  [BT*NHEADS*DSTATE];
__device__ float  g_coef[BT*NHEADS*4];
__device__ float  g_par [BT*NPAR];
__device__ float  g_x1  [BT*DMODEL];
__device__ __half g_projh[BT*DGV];            // silu(gate) | vraw (fp16)
__device__ __half g_xnh [BT*DMODEL];
__device__ __half g_vh  [BT*DINNER];
__device__ __half g_yh  [BT*DINNER];
__device__ __half g_hh  [BT*DMODEL];
__device__ __half g_ffh [BT*DFF];
__device__ __half g_wh  [W_TOTAL];

// ---------------- device math helpers ----------------
__device__ __forceinline__ float sigmoidf_(float x) { return 1.0f / (1.0f + expf(-x)); }
__device__ __forceinline__ float siluf_(float x)    { return x * sigmoidf_(x); }
__device__ __forceinline__ float softplusf_(float x){ return fmaxf(x, 0.0f) + log1pf(expf(-fabsf(x))); }
__device__ __forceinline__ float geluf_(float x) {
    float x3 = x * x * x;
    float t  = tanhf(0.7978845608028654f * (x + 0.044715f * x3));
    return 0.5f * x * (1.0f + t);
}

// ---------------- rmsnorm core (device) ----------------
__device__ __forceinline__ void rmsnorm_core(const float* __restrict__ x,
                                             const float* __restrict__ nw,
                                             __half* __restrict__ out,
                                             int row, float* sh) {
    const float* xr = x + (size_t)row * DMODEL;
    __half*    orow = out + (size_t)row * DMODEL;
    int tid = threadIdx.x;
    float xv[3];
    float ss = 0.0f;
#pragma unroll
    for (int j = 0; j < 3; j++) {
        int i = tid + j * 256;
        float v = xr[i];
        xv[j] = v;
        ss += v * v;
    }
#pragma unroll
    for (int off = 16; off > 0; off >>= 1)
        ss += __shfl_xor_sync(0xffffffff, ss, off);
    int lane = tid & 31, wid = tid >> 5;
    if (lane == 0) sh[wid] = ss;
    __syncthreads();
    if (wid == 0) {
        float v = (lane < 8) ? sh[lane] : 0.0f;
#pragma unroll
        for (int off = 4; off > 0; off >>= 1)
            v += __shfl_xor_sync(0xffffffff, v, off);
        if (lane == 0) sh[0] = rsqrtf(v * (1.0f / DMODEL) + 1e-6f);
    }
    __syncthreads();
    float s = sh[0];
#pragma unroll
    for (int j = 0; j < 3; j++) {
        int i = tid + j * 256;
        orow[i] = __float2half(xv[j] * s * nw[i]);
    }
}

// ---------------- fused: all weight transposes + rmsnorm1, one launch --------
__global__ void prep_kernel(const float* __restrict__ w_in,
                            const float* __restrict__ w_bc,
                            const float* __restrict__ w_out,
                            const float* __restrict__ ff1,
                            const float* __restrict__ ff2,
                            __half* __restrict__ wh,
                            const float* __restrict__ x,
                            const float* __restrict__ norm1_w,
                            __half* __restrict__ xnh) {
    __shared__ float tile[32][33];
    __shared__ float sh[8];
    int id = blockIdx.x;
    int tid = threadIdx.x;

    if (id >= T5_END) {
        rmsnorm_core(x, norm1_w, xnh, id - T5_END, sh);
        return;
    }
    const float* src; __half* dst; int K, N, Nt;
    if (id < T1_END)      {               src = w_in;  dst = wh + W_IN_OFF;  K = DMODEL; N = DPROJ; Nt = 98; }
    else if (id < T2_END) { id -= T1_END; src = w_bc;  dst = wh + W_BC_OFF;  K = DINNER; N = 384;   Nt = 12; }
    else if (id < T3_END) { id -= T2_END; src = w_out; dst = wh + W_OUT_OFF; K = DINNER; N = DMODEL;Nt = 24; }
    else if (id < T4_END) { id -= T3_END; src = ff1;   dst = wh + FF1_OFF;   K = DMODEL; N = DFF;   Nt = 96; }
    else                  { id -= T4_END; src = ff2;   dst = wh + FF2_OFF;   K = DFF;    N = DMODEL;Nt = 24; }
    int nb = (id % Nt) * 32, kb = (id / Nt) * 32;
    int tx = tid & 31, ty = tid >> 5;   // 32 x 8
#pragma unroll
    for (int j = 0; j < 32; j += 8) {
        int k = kb + ty + j, n = nb + tx;
        tile[ty + j][tx] = (k < K && n < N) ? src[(size_t)k * N + n] : 0.0f;
    }
    __syncthreads();
#pragma unroll
    for (int j = 0; j < 32; j += 8) {
        int n = nb + ty + j, k = kb + tx;
        if (n < N && k < K) dst[(size_t)n * K + k] = __float2half(tile[tx][ty + j]);
    }
}

// ---------------- rmsnorm standalone (rmsnorm2) ----------------
__global__ void rmsnorm_kernel(const float* __restrict__ x,
                               const float* __restrict__ nw,
                               __half* __restrict__ out) {
    __shared__ float sh[8];
    rmsnorm_core(x, nw, out, blockIdx.x, sh);
}

// ============================================================================
// fp16 mma.sync GEMM (m16n8k16), BK=64, 3-stage cp.async pipeline.
//   smem rows padded to 72 halves; EPI as before.
// ============================================================================
#define ASTRH  72
#define STAGES 3

template <int BN, int WM, int WN, int EPI>
__global__ void __launch_bounds__(256)
gemm_fp16(const __half* __restrict__ A,
          const __half* __restrict__ Bt,
          void* __restrict__ Cv,
          int M, int N, int K,
          const float* __restrict__ bias,
          const float* __restrict__ res,
          float* __restrict__ aux) {
    constexpr int MT   = WM / 16;
    constexpr int NT   = WN / 8;
    constexpr int WGM  = 128 / WM;
    constexpr int ASTG = 128 * ASTRH;
    constexpr int BSTG = BN * ASTRH;
    constexpr int BCH  = (BN * 8) / 256;

    extern __shared__ __half dsm[];
    __half* As = dsm;
    __half* Bs = dsm + STAGES * ASTG;

    const int tid  = threadIdx.x;
    const int warp = tid >> 5;
    const int lane = tid & 31;
    const int g    = lane >> 2;
    const int t    = lane & 3;
    const int sel  = lane >> 3;

    const int wm = (warp % WGM) * WM;
    const int wn = (warp / WGM) * WN;
    const int bm = blockIdx.y * 128;
    const int bn = blockIdx.x * BN;

    const int lrow  = wm + ((sel & 1) << 3) + (lane & 7);
    const int lcolh = (sel >> 1) << 3;
    const int brow  = ((sel >> 1) << 3) + (lane & 7);
    const int bcolh = (sel & 1) << 3;

    const uint32_t as0 = (uint32_t)__cvta_generic_to_shared(As);
    const uint32_t bs0 = (uint32_t)__cvta_generic_to_shared(Bs);

    float acc[MT][NT][4];
#pragma unroll
    for (int i = 0; i < MT; i++)
#pragma unroll
        for (int j = 0; j < NT; j++)
#pragma unroll
            for (int r = 0; r < 4; r++) acc[i][j][r] = 0.0f;

    const int nkt = K >> 6;       // BK = 64

    auto issue = [&](int kt, int buf) {
        int k0 = kt << 6;
#pragma unroll
        for (int i = 0; i < 4; i++) {
            int idx = tid + (i << 8);
            int row = idx >> 3, c16 = idx & 7;
            const __half* src = &A[(size_t)(bm + row) * K + k0 + c16 * 8];
            uint32_t dst = as0 + (uint32_t)(buf * ASTG + row * ASTRH + c16 * 8) * 2u;
            asm volatile("cp.async.cg.shared.global [%0], [%1], 16;"
                         :: "r"(dst), "l"(src));
        }
#pragma unroll
        for (int i = 0; i < BCH; i++) {
            int idx = tid + (i << 8);
            int row = idx >> 3, c16 = idx & 7;
            int n = bn + row;
            const __half* src = &Bt[(size_t)(n < N ? n : 0) * K + k0 + c16 * 8];
            int sz = (n < N) ? 16 : 0;
            uint32_t dst = bs0 + (uint32_t)(buf * BSTG + row * ASTRH + c16 * 8) * 2u;
            asm volatile("cp.async.cg.shared.global [%0], [%1], 16, %2;"
                         :: "r"(dst), "l"(src), "r"(sz));
        }
        asm volatile("cp.async.commit_group;" ::: "memory");
    };

#pragma unroll
    for (int s = 0; s < STAGES - 1; ++s)
        if (s < nkt) issue(s, s);

    int buf = 0;
    for (int kt = 0; kt < nkt; ++kt) {
        asm volatile("cp.async.wait_group %0;" :: "n"(STAGES - 2) : "memory");
        __syncthreads();
        if (kt + STAGES - 1 < nkt)
            issue(kt + STAGES - 1, (kt + STAGES - 1) % STAGES);

#pragma unroll
        for (int ks = 0; ks < 4; ks++) {
            uint32_t a[MT][4];
#pragma unroll
            for (int mi = 0; mi < MT; mi++) {
                uint32_t addr = as0 + (uint32_t)(buf * ASTG +
                                (lrow + mi * 16) * ASTRH + ks * 16 + lcolh) * 2u;
                asm volatile(
                    "ldmatrix.sync.aligned.m8n8.x4.shared.b16 {%0,%1,%2,%3}, [%4];"
                    : "=r"(a[mi][0]), "=r"(a[mi][1]), "=r"(a[mi][2]), "=r"(a[mi][3])
                    : "r"(addr));
            }
            uint32_t b[NT][2];
#pragma unroll
            for (int nt2 = 0; nt2 < NT / 2; nt2++) {
                uint32_t addr = bs0 + (uint32_t)(buf * BSTG +
                                (wn + nt2 * 16 + brow) * ASTRH + ks * 16 + bcolh) * 2u;
                asm volatile(
                    "ldmatrix.sync.aligned.m8n8.x4.shared.b16 {%0,%1,%2,%3}, [%4];"
                    : "=r"(b[nt2 * 2][0]), "=r"(b[nt2 * 2][1]),
                      "=r"(b[nt2 * 2 + 1][0]), "=r"(b[nt2 * 2 + 1][1])
                    : "r"(addr));
            }
#pragma unroll
            for (int ni = 0; ni < NT; ni++)
#pragma unroll
                for (int mi = 0; mi < MT; mi++) {
                    asm volatile(
                        "mma.sync.aligned.m16n8k16.row.col.f32.f16.f16.f32 "
                        "{%0,%1,%2,%3},{%4,%5,%6,%7},{%8,%9},{%0,%1,%2,%3};"
                        : "+f"(acc[mi][ni][0]), "+f"(acc[mi][ni][1]),
                          "+f"(acc[mi][ni][2]), "+f"(acc[mi][ni][3])
                        : "r"(a[mi][0]), "r"(a[mi][1]), "r"(a[mi][2]), "r"(a[mi][3]),
                          "r"(b[ni][0]), "r"(b[ni][1]));
                }
        }
        buf = (buf + 1 == STAGES) ? 0 : buf + 1;
    }

    // ---- epilogue ----
    float*  Cf = (float*)Cv;
    __half* Ch = (__half*)Cv;
#pragma unroll
    for (int mi = 0; mi < MT; mi++) {
        int row0 = bm + wm + mi * 16 + g;
        int row1 = row0 + 8;
#pragma unroll
        for (int ni = 0; ni < NT; ni++) {
            int col = bn + wn + ni * 8 + 2 * t;
            if (col < N) {
                float2 p0 = make_float2(acc[mi][ni][0], acc[mi][ni][1]);
                float2 p1 = make_float2(acc[mi][ni][2], acc[mi][ni][3]);
                if (EPI == 1) {
                    float b0v = bias[col], b1v = bias[col + 1];
                    *reinterpret_cast<__half2*>(&Ch[(size_t)row0 * N + col]) =
                        __floats2half2_rn(geluf_(p0.x + b0v), geluf_(p0.y + b1v));
                    *reinterpret_cast<__half2*>(&Ch[(size_t)row1 * N + col]) =
                        __floats2half2_rn(geluf_(p1.x + b0v), geluf_(p1.y + b1v));
                } else if (EPI == 5) {
                    if (col < DGV) {
                        if (col < DINNER) {
                            p0.x = siluf_(p0.x); p0.y = siluf_(p0.y);
                            p1.x = siluf_(p1.x); p1.y = siluf_(p1.y);
                        }
                        *reinterpret_cast<__half2*>(&Ch[(size_t)row0 * DGV + col]) =
                            __floats2half2_rn(p0.x, p0.y);
                        *reinterpret_cast<__half2*>(&Ch[(size_t)row1 * DGV + col]) =
                            __floats2half2_rn(p1.x, p1.y);
                    } else {
                        int pc = col - DGV;
                        *reinterpret_cast<float2*>(&aux[(size_t)row0 * NPAR + pc]) = p0;
                        *reinterpret_cast<float2*>(&aux[(size_t)row1 * NPAR + pc]) = p1;
                    }
                } else {
                    if (EPI == 2) {
                        float2 r0 = *reinterpret_cast<const float2*>(&res[(size_t)row0 * N + col]);
                        float2 r1 = *reinterpret_cast<const float2*>(&res[(size_t)row1 * N + col]);
                        p0.x += bias[col] + r0.x; p0.y += bias[col + 1] + r0.y;
                        p1.x += bias[col] + r1.x; p1.y += bias[col + 1] + r1.y;
                    } else if (EPI == 3) {
                        float2 r0 = *reinterpret_cast<const float2*>(&res[(size_t)row0 * N + col]);
                        float2 r1 = *reinterpret_cast<const float2*>(&res[(size_t)row1 * N + col]);
                        p0.x += r0.x; p0.y += r0.y;
                        p1.x += r1.x; p1.y += r1.y;
                    }
                    *reinterpret_cast<float2*>(&Cf[(size_t)row0 * N + col]) = p0;
                    *reinterpret_cast<float2*>(&Cf[(size_t)row1 * N + col]) = p1;
                }
            }
        }
    }
}

// ---------------- smem-tiled conv+silu -> fp16 v (fp16 vraw input) -----------
__global__ void __launch_bounds__(256)
conv_silu_kernel(const __half* __restrict__ projh,
                 const float* __restrict__ conv_w,
                 __half* __restrict__ vh) {
    __shared__ float shP[67 * 64];
    __shared__ float shW[4][64];
    const int tid = threadIdx.x;
    const int bt0 = blockIdx.x * 64;
    const int c0  = blockIdx.y * 64;
    const bool seqstart = (bt0 % SEQ) == 0;

    {
        int c = tid >> 2, k = tid & 3;
        shW[k][c] = conv_w[(c0 + c) * DCONV + k];
    }
#pragma unroll
    for (int pass = 0; pass < 3; pass++) {
        int idx = pass * 256 + tid;
        if (idx < 67 * 8) {
            int j = idx >> 3, hc = idx & 7;
            uint4 hv = make_uint4(0u, 0u, 0u, 0u);
            if (!(seqstart && j < 3))
                hv = *reinterpret_cast<const uint4*>(
                    &projh[(size_t)(bt0 - 3 + j) * DGV + DINNER + c0 + hc * 8]);
            const __half2* hp = reinterpret_cast<const __half2*>(&hv);
            float* dp = &shP[j * 64 + hc * 8];
#pragma unroll
            for (int q = 0; q < 4; q++) {
                float2 f = __half22float2(hp[q]);
                dp[2 * q]     = f.x;
                dp[2 * q + 1] = f.y;
            }
        }
    }
    __syncthreads();
#pragma unroll
    for (int pass = 0; pass < 16; pass++) {
        int idx = pass * 256 + tid;
        int r = idx >> 6, c = idx & 63;
        float acc = 0.0f;
#pragma unroll
        for (int k = 0; k < 4; k++)
            acc = fmaf(shP[(r + k) * 64 + c], shW[k][c], acc);
        vh[(size_t)(bt0 + r) * DINNER + c0 + c] = __float2half(siluf_(acc));
    }
}

// ---------------- B/C normalize + scan coefficients (f32 params) -------------
__global__ void bcparams_kernel(const float* __restrict__ bc,
                                const float* __restrict__ par,
                                float* __restrict__ Bn,
                                float* __restrict__ Cn,
                                float* __restrict__ coef) {
    int idx = blockIdx.x * blockDim.x + threadIdx.x;
    if (idx >= BT * NHEADS) return;
    int h  = idx % NHEADS;
    int bt = idx / NHEADS;

    const float* p = bc + (size_t)bt * (2 * NHEADS * DSTATE) + h * 16;
    float bl[8], cl[8];
    float ssb = 0.0f, ssc = 0.0f;
#pragma unroll
    for (int n = 0; n < 8; n++) {
        bl[n] = p[n];     ssb = fmaf(bl[n], bl[n], ssb);
        cl[n] = p[8 + n]; ssc = fmaf(cl[n], cl[n], ssc);
    }
    float rb = rsqrtf(ssb + 1e-12f);
    float rc = rsqrtf(ssc + 1e-12f);
#pragma unroll
    for (int n = 0; n < 8; n++) {
        Bn[(size_t)idx * 8 + n] = bl[n] * rb;
        Cn[(size_t)idx * 8 + n] = cl[n] * rc;
    }
    float p0 = par[(size_t)bt * NPAR + h * 2 + 0];
    float p1 = par[(size_t)bt * NPAR + h * 2 + 1];
    float Aq = softplusf_(p0);
    float dt = sigmoidf_(p1);
    float S  = 1.0f / (1.0f + dt * dt * Aq);
    coef[(size_t)idx * 4 + 0] = S;
    coef[(size_t)idx * 4 + 1] = S * dt * Aq;
    coef[(size_t)idx * 4 + 2] = S * dt;
    coef[(size_t)idx * 4 + 3] = dt;
}

// ---------------- sequential LinOSS-IM scan, 128 threads/block ---------------
__global__ void scan_kernel(const float* __restrict__ Bn,
                            const float* __restrict__ Cn,
                            const float* __restrict__ coef,
                            const __half* __restrict__ vh,
                            const __half* __restrict__ projh,  // gate silu'd fp16
                            const float* __restrict__ Dsk,
                            __half* __restrict__ yh) {
    int bh = blockIdx.x;                  // 0..47
    int b = bh / NHEADS, h = bh % NHEADS;
    int tid  = threadIdx.x;               // 0..127
    int p    = tid >> 1;                   // 0..63
    int half = tid & 1;                    // state half
    float dskip = Dsk[h];

    __shared__ float4 shB[64 * 2];
    __shared__ float4 shC[64 * 2];
    __shared__ float4 shCo[64];
    __shared__ float  shU[64 * 64];
    __shared__ float  shG[64 * 64];

    float z[4], xs[4];
#pragma unroll
    for (int n = 0; n < 4; n++) { z[n] = 0.0f; xs[n] = 0.0f; }

    for (int chunk = 0; chunk < SEQ / 64; chunk++) {
        __syncthreads();
        {
            int tB  = chunk * 64 + p;
            int idx = (b * SEQ + tB) * NHEADS + h;
            shB[p * 2 + half] = *reinterpret_cast<const float4*>(&Bn[(size_t)idx * 8 + half * 4]);
            shC[p * 2 + half] = *reinterpret_cast<const float4*>(&Cn[(size_t)idx * 8 + half * 4]);
            if (half == 0)
                shCo[p] = *reinterpret_cast<const float4*>(&coef[(size_t)idx * 4]);
        }
        int base = b * SEQ + chunk * 64;
#pragma unroll
        for (int pass = 0; pass < 4; pass++) {
            int idx = pass * 128 + tid;
            int row = idx >> 3, hc = idx & 7;
            uint4 hv = *reinterpret_cast<const uint4*>(
                &vh[(size_t)(base + row) * DINNER + h * DHEAD + hc * 8]);
            const __half2* hp = reinterpret_cast<const __half2*>(&hv);
            float* du = &shU[row * 64 + hc * 8];
#pragma unroll
            for (int j = 0; j < 4; j++) {
                float2 f = __half22float2(hp[j]);
                du[2 * j]     = f.x;
                du[2 * j + 1] = f.y;
            }
        }
#pragma unroll
        for (int pass = 0; pass < 4; pass++) {
            int idx = pass * 128 + tid;
            int row = idx >> 3, hc = idx & 7;
            uint4 hv = *reinterpret_cast<const uint4*>(
                &projh[(size_t)(base + row) * DGV + h * DHEAD + hc * 8]);
            const __half2* hp = reinterpret_cast<const __half2*>(&hv);
            float* dg = &shG[row * 64 + hc * 8];
#pragma unroll
            for (int j = 0; j < 4; j++) {
                float2 f = __half22float2(hp[j]);
                dg[2 * j]     = f.x;
                dg[2 * j + 1] = f.y;
            }
        }
        __syncthreads();

#pragma unroll 4
        for (int i = 0; i < 64; i++) {
            float4 co = shCo[i];
            float  u  = shU[i * 64 + p];
            float4 bv = shB[i * 2 + half];
            float4 cv = shC[i * 2 + half];
            float bb[4] = {bv.x, bv.y, bv.z, bv.w};
            float cc[4] = {cv.x, cv.y, cv.z, cv.w};
            float yv = 0.0f;
#pragma unroll
            for (int n = 0; n < 4; n++) {
                z[n]  = fmaf(co.x, z[n], fmaf(-co.y, xs[n], co.z * bb[n] * u));
                xs[n] = fmaf(co.w, z[n], xs[n]);
                yv    = fmaf(cc[n], xs[n], yv);
            }
            yv += __shfl_xor_sync(0xffffffff, yv, 1);
            if (half == 0) {
                float sg = shG[i * 64 + p];
                yh[(size_t)(base + i) * DINNER + h * DHEAD + p] =
                    __float2half((yv + dskip * u) * sg);
            }
        }
    }
}

// ---------------- launch ----------------
extern "C" void kernel_launch(void* const* d_in, const int* in_sizes, int n_in,
                              void* d_out, int out_size) {
    const float* x       = (const float*)d_in[0];
    const float* norm1_w = (const float*)d_in[1];
    const float* w_in    = (const float*)d_in[2];
    const float* conv_w  = (const float*)d_in[3];
    const float* w_bc    = (const float*)d_in[4];
    const float* D_skip  = (const float*)d_in[5];
    const float* w_out   = (const float*)d_in[6];
    const float* norm2_w = (const float*)d_in[7];
    const float* ff_w1   = (const float*)d_in[8];
    const float* ff_b1   = (const float*)d_in[9];
    const float* ff_w2   = (const float*)d_in[10];
    const float* ff_b2   = (const float*)d_in[11];
    float* out = (float*)d_out;

    float *bc, *Bn, *Cn, *coef, *par, *x1;
    __half *projh, *xnh, *vh, *yh, *hh, *ffh, *wh;
    cudaGetSymbolAddress((void**)&bc,    g_bc);
    cudaGetSymbolAddress((void**)&Bn,    g_Bn);
    cudaGetSymbolAddress((void**)&Cn,    g_Cn);
    cudaGetSymbolAddress((void**)&coef,  g_coef);
    cudaGetSymbolAddress((void**)&par,   g_par);
    cudaGetSymbolAddress((void**)&x1,    g_x1);
    cudaGetSymbolAddress((void**)&projh, g_projh);
    cudaGetSymbolAddress((void**)&xnh,   g_xnh);
    cudaGetSymbolAddress((void**)&vh,    g_vh);
    cudaGetSymbolAddress((void**)&yh,    g_yh);
    cudaGetSymbolAddress((void**)&hh,    g_hh);
    cudaGetSymbolAddress((void**)&ffh,   g_ffh);
    cudaGetSymbolAddress((void**)&wh,    g_wh);

    const int SM128 = STAGES * (128 * ASTRH + 128 * ASTRH) * 2;  // 110592 B
    const int SM64  = STAGES * (128 * ASTRH + 64 * ASTRH)  * 2;  // 82944 B
    cudaFuncSetAttribute(gemm_fp16<128, 64, 32, 5>,
                         cudaFuncAttributeMaxDynamicSharedMemorySize, SM128);
    cudaFuncSetAttribute(gemm_fp16<128, 64, 32, 1>,
                         cudaFuncAttributeMaxDynamicSharedMemorySize, SM128);
    cudaFuncSetAttribute(gemm_fp16<64, 32, 32, 0>,
                         cudaFuncAttributeMaxDynamicSharedMemorySize, SM64);
    cudaFuncSetAttribute(gemm_fp16<64, 32, 32, 2>,
                         cudaFuncAttributeMaxDynamicSharedMemorySize, SM64);
    cudaFuncSetAttribute(gemm_fp16<64, 32, 32, 3>,
                         cudaFuncAttributeMaxDynamicSharedMemorySize, SM64);

    // 0. transposes + rmsnorm1 fused (rmsnorm rides the transpose DRAM shadow)
    prep_kernel<<<TR_BLOCKS, 256>>>(w_in, w_bc, w_out, ff_w1, ff_w2, wh,
                                    x, norm1_w, xnh);
    // 1. proj = xn @ w_in (4096 x 3120 x 768): silu(gate)|vraw fp16, params f32
    gemm_fp16<128, 64, 32, 5><<<dim3((DPROJ + 127) / 128, BT / 128), 256, SM128>>>(
        xnh, wh + W_IN_OFF, projh, BT, DPROJ, DMODEL, nullptr, nullptr, par);
    // 2. smem-tiled conv+silu -> fp16 v
    conv_silu_kernel<<<dim3(BT / 64, DINNER / 64), 256>>>(projh, conv_w, vh);
    // 3. bc = v @ w_bc (4096 x 384 x 1536), f32 out
    gemm_fp16<64, 32, 32, 0><<<dim3((2 * NHEADS * DSTATE) / 64, BT / 128), 256, SM64>>>(
        vh, wh + W_BC_OFF, bc, BT, 2 * NHEADS * DSTATE, DINNER, nullptr, nullptr, nullptr);
    // 4. normalize B/C + scan coefficients
    bcparams_kernel<<<(BT * NHEADS + 127) / 128, 128>>>(bc, par, Bn, Cn, coef);
    // 5. sequential scan (128 thr/block, 2 states/thread) -> fp16 y
    scan_kernel<<<BATCH * NHEADS, 128>>>(Bn, Cn, coef, vh, projh, D_skip, yh);
    // 6. x1 = x + y @ w_out (4096 x 768 x 1536), f32 out [BN=64: wave balance]
    gemm_fp16<64, 32, 32, 3><<<dim3(DMODEL / 64, BT / 128), 256, SM64>>>(
        yh, wh + W_OUT_OFF, x1, BT, DMODEL, DINNER, nullptr, x, nullptr);
    // 7. rmsnorm2 -> fp16
    rmsnorm_kernel<<<BT, 256>>>(x1, norm2_w, hh);
    // 8. ff = gelu(h @ ff_w1 + b1) (4096 x 3072 x 768), fp16 out
    gemm_fp16<128, 64, 32, 1><<<dim3(DFF / 128, BT / 128), 256, SM128>>>(
        hh, wh + FF1_OFF, ffh, BT, DFF, DMODEL, ff_b1, nullptr, nullptr);
    // 9. out = x1 + ff @ ff_w2 + b2 (4096 x 768 x 3072), f32 out [BN=64]
    gemm_fp16<64, 32, 32, 2><<<dim3(DMODEL / 64, BT / 128), 256, SM64>>>(
        ffh, wh + FF2_OFF, out, BT, DMODEL, DFF, ff_b2, x1, nullptr);
}